// round 16
// baseline (speedup 1.0000x reference)
#include <cuda_runtime.h>
#include <cuda_bf16.h>
#include <cstdint>

#define NN 8192
#define INF 512
#define OF 128

// ---------------- scratch (device globals; no allocation) ----------------
__device__ __nv_bfloat16 g_WT[(size_t)OF * INF];   // W^T bf16 [feat][k]
__device__ uint8_t g_Wh8[(size_t)OF * NN];         // Wh e4m3 [feat][node]
__device__ float g_Wh1[NN];
__device__ float g_Wh2[NN];

#define K8L2E 11.541560327111708f    // 8*log2(e)
#define K8L2E5 2.3083120654223416f   // 0.2 * 8*log2(e)
#define K02H2  0x32663266u           // half2(0.2, 0.2)
#define MAGIC2 0x64006400u           // half2(1024.0, 1024.0)

// ---------------- helpers ----------------
__device__ __forceinline__ uint32_t pack2(float lo, float hi) {
    uint32_t r;
    asm("cvt.rn.bf16x2.f32 %0, %1, %2;" : "=r"(r) : "f"(hi), "f"(lo));
    return r;
}
__device__ __forceinline__ uint32_t f2h2(float v) {
    uint32_t r;
    asm("{ .reg .f16 h; cvt.rn.f16.f32 h, %1; mov.b32 %0, {h, h}; }" : "=r"(r) : "f"(v));
    return r;
}
__device__ __forceinline__ uint32_t fh2(float hi, float lo) {
    uint32_t r;
    asm("cvt.rn.f16x2.f32 %0, %1, %2;" : "=r"(r) : "f"(hi), "f"(lo));
    return r;
}
__device__ __forceinline__ void sts32u(uint32_t a, uint32_t v) {
    asm volatile("st.shared.b32 [%0], %1;" :: "r"(a), "r"(v) : "memory");
}
__device__ __forceinline__ void sts32f(uint32_t a, float v) {
    asm volatile("st.shared.f32 [%0], %1;" :: "r"(a), "f"(v) : "memory");
}
__device__ __forceinline__ void sts64(uint32_t a, uint32_t x, uint32_t y) {
    asm volatile("st.shared.v2.b32 [%0], {%1,%2};" :: "r"(a), "r"(x), "r"(y) : "memory");
}
__device__ __forceinline__ void sts128u(uint32_t a, uint32_t x, uint32_t y,
                                        uint32_t z, uint32_t w) {
    asm volatile("st.shared.v4.b32 [%0], {%1,%2,%3,%4};"
                 :: "r"(a), "r"(x), "r"(y), "r"(z), "r"(w) : "memory");
}
__device__ __forceinline__ float lds32f(uint32_t a) {
    float v; asm volatile("ld.shared.f32 %0, [%1];" : "=f"(v) : "r"(a)); return v;
}
__device__ __forceinline__ uint2 lds64u(uint32_t a) {
    uint2 v;
    asm volatile("ld.shared.v2.b32 {%0,%1}, [%2];" : "=r"(v.x), "=r"(v.y) : "r"(a));
    return v;
}
__device__ __forceinline__ void ldsm4(uint32_t* r, uint32_t a) {
    asm volatile("ldmatrix.sync.aligned.m8n8.x4.shared.b16 {%0,%1,%2,%3}, [%4];"
                 : "=r"(r[0]), "=r"(r[1]), "=r"(r[2]), "=r"(r[3]) : "r"(a));
}
__device__ __forceinline__ void mma16816(float* d, const uint32_t* a, uint32_t b0, uint32_t b1) {
    asm volatile(
        "mma.sync.aligned.m16n8k16.row.col.f32.bf16.bf16.f32 "
        "{%0,%1,%2,%3}, {%4,%5,%6,%7}, {%8,%9}, {%0,%1,%2,%3};"
        : "+f"(d[0]), "+f"(d[1]), "+f"(d[2]), "+f"(d[3])
        : "r"(a[0]), "r"(a[1]), "r"(a[2]), "r"(a[3]), "r"(b0), "r"(b1));
}
__device__ __forceinline__ void mma_fp8(float* d, const uint32_t* a, uint32_t b0, uint32_t b1) {
    asm volatile(
        "mma.sync.aligned.m16n8k32.row.col.f32.e4m3.e4m3.f32 "
        "{%0,%1,%2,%3}, {%4,%5,%6,%7}, {%8,%9}, {%0,%1,%2,%3};"
        : "+f"(d[0]), "+f"(d[1]), "+f"(d[2]), "+f"(d[3])
        : "r"(a[0]), "r"(a[1]), "r"(a[2]), "r"(a[3]), "r"(b0), "r"(b1));
}
__device__ __forceinline__ void cp16(uint32_t s, const void* g) {
    asm volatile("cp.async.cg.shared.global [%0], [%1], 16;" :: "r"(s), "l"(g) : "memory");
}
// half2 log-domain build: byte = round(max(max(ws+c1, 0.2*ws+c2), 0)) via +1024 magic
__device__ __forceinline__ uint32_t build4h(uint32_t ws01, uint32_t ws23,
                                            uint32_t c1, uint32_t c2, int4 a4) {
    uint32_t t0, t1, m0, m1;
    asm("add.f16x2 %0, %1, %2;" : "=r"(t0) : "r"(ws01), "r"(c1));
    asm("fma.rn.f16x2 %0, %1, %2, %3;" : "=r"(t1) : "r"(ws01), "r"(K02H2), "r"(c2));
    asm("max.f16x2 %0, %1, %2;" : "=r"(m0) : "r"(t0), "r"(t1));
    asm("max.f16x2 %0, %1, %2;" : "=r"(m0) : "r"(m0), "r"(0u));
    asm("add.f16x2 %0, %1, %2;" : "=r"(m0) : "r"(m0), "r"(MAGIC2));
    asm("add.f16x2 %0, %1, %2;" : "=r"(t0) : "r"(ws23), "r"(c1));
    asm("fma.rn.f16x2 %0, %1, %2, %3;" : "=r"(t1) : "r"(ws23), "r"(K02H2), "r"(c2));
    asm("max.f16x2 %0, %1, %2;" : "=r"(m1) : "r"(t0), "r"(t1));
    asm("max.f16x2 %0, %1, %2;" : "=r"(m1) : "r"(m1), "r"(0u));
    asm("add.f16x2 %0, %1, %2;" : "=r"(m1) : "r"(m1), "r"(MAGIC2));
    uint32_t pk = __byte_perm(m0, m1, 0x6420);   // mantissa byte0 of each half lane
    uint32_t m = __byte_perm(__byte_perm(a4.x, a4.y, 0x0040),
                             __byte_perm(a4.z, a4.w, 0x0040), 0x5410);
    return pk & (m * 255u);
}

// ================= K0: prep — W->W^T bf16 only =================
__global__ __launch_bounds__(256) void k_prep(const float* __restrict__ W) {
    const int b = blockIdx.x, t = threadIdx.x;
    int idx = b * 1024 + t * 4;
    int k = idx >> 7, f = idx & 127;
    float4 v = *reinterpret_cast<const float4*>(&W[(size_t)k * OF + f]);
    g_WT[(size_t)(f + 0) * INF + k] = __float2bfloat16(v.x);
    g_WT[(size_t)(f + 1) * INF + k] = __float2bfloat16(v.y);
    g_WT[(size_t)(f + 2) * INF + k] = __float2bfloat16(v.z);
    g_WT[(size_t)(f + 3) * INF + k] = __float2bfloat16(v.w);
}

// ================= K1: Wh = h @ W via bf16 mma.sync, + Wh1/Wh2 (smem combine) =====
#define GSA 0u
#define GSB 16384u
#define GSV 49152u
#define GSR (GSV + 1024u)            // Wh1 partials 512B, Wh2 partials 512B
#define GSM (49152 + 2048 + 128)

__device__ __forceinline__ void issue_Bg(uint32_t sb, int ko, int t) {
    const uint32_t bbuf = sb + GSB + (uint32_t)(ko & 1) * 16384u;
#pragma unroll
    for (int s = 0; s < 4; s++) {
        int c = t + s * 256;
        int f = c >> 3, u = c & 7;
        cp16(bbuf + (uint32_t)f * 128u + (((uint32_t)u * 16u) ^ ((uint32_t)(f & 7) << 4)),
             &g_WT[(size_t)f * INF + ko * 64 + u * 8]);
    }
    asm volatile("cp.async.commit_group;" ::: "memory");
}
__device__ __forceinline__ void lda2(float4* d, const float* __restrict__ h,
                                     int i0, int ko, int t) {
#pragma unroll
    for (int s = 0; s < 2; s++) {
        int c = t + s * 256;
        int r = c >> 3, u = c & 7;
        const float* src = &h[(size_t)(i0 + r) * INF + ko * 64 + u * 8];
        d[s * 2]     = *reinterpret_cast<const float4*>(src);
        d[s * 2 + 1] = *reinterpret_cast<const float4*>(src + 4);
    }
}
__device__ __forceinline__ void sta2(uint32_t sb, int ko, int t, const float4* d) {
    const uint32_t abuf = sb + GSA + (uint32_t)(ko & 1) * 8192u;
#pragma unroll
    for (int s = 0; s < 2; s++) {
        int c = t + s * 256;
        int r = c >> 3, u = c & 7;
        sts128u(abuf + (uint32_t)r * 128u + (((uint32_t)u * 16u) ^ ((uint32_t)(r & 7) << 4)),
                pack2(d[s * 2].x, d[s * 2].y), pack2(d[s * 2].z, d[s * 2].w),
                pack2(d[s * 2 + 1].x, d[s * 2 + 1].y), pack2(d[s * 2 + 1].z, d[s * 2 + 1].w));
    }
}

__global__ void __launch_bounds__(256, 1) k_gemm(const float* __restrict__ a,
                                                 const float* __restrict__ h) {
    extern __shared__ char dsm[];
    uint32_t sb = (uint32_t)__cvta_generic_to_shared(dsm);
    sb = (sb + 127u) & ~127u;

    const int t = threadIdx.x, w = t >> 5, l = t & 31;
    const int i0 = blockIdx.x * 64;
    const int m0 = (w >> 1) * 16, n0 = (w & 1) * 64;

    if (t < 256) sts32f(sb + GSV + (uint32_t)t * 4u, a[t]);

    float4 ra[4];
    lda2(ra, h, i0, 0, t);
    sta2(sb, 0, t, ra);            // A(0) -> buf0
    lda2(ra, h, i0, 1, t);         // prefetch A(1)
    issue_Bg(sb, 0, t);

    const int q = l >> 3, lq = l & 7;
    const uint32_t keyL = (uint32_t)lq << 4;
    const int arow = m0 + (q & 1) * 8 + lq;
    const uint32_t paA = (uint32_t)arow * 128u;
    const uint32_t offA = ((uint32_t)(q >> 1) * 16u);
    const int bq_f = (q >> 1) * 8 + lq;
    const uint32_t offBk = ((uint32_t)(q & 1) * 16u);

    float acc[8][4];
#pragma unroll
    for (int nt = 0; nt < 8; nt++)
#pragma unroll
        for (int c = 0; c < 4; c++) acc[nt][c] = 0.f;

#pragma unroll 1
    for (int ko = 0; ko < 8; ko++) {
        asm volatile("cp.async.wait_group 0;" ::: "memory");
        __syncthreads();
        if (ko < 7) {
            issue_Bg(sb, ko + 1, t);
            sta2(sb, ko + 1, t, ra);           // A(ko+1) -> other buf
        }
        if (ko < 6) lda2(ra, h, i0, ko + 2, t);  // prefetch A(ko+2)

        const uint32_t abuf = sb + GSA + (uint32_t)(ko & 1) * 8192u;
        const uint32_t bbuf = sb + GSB + (uint32_t)(ko & 1) * 16384u;
#pragma unroll
        for (int kk = 0; kk < 4; kk++) {
            uint32_t af[4];
            ldsm4(af, abuf + paA + (((uint32_t)kk * 32u + offA) ^ keyL));
            uint32_t bfr[4][4];
#pragma unroll
            for (int i = 0; i < 4; i++) {
                int f = n0 + i * 16 + bq_f;
                ldsm4(bfr[i], bbuf + (uint32_t)f * 128u
                              + (((uint32_t)kk * 32u + offBk) ^ ((uint32_t)(f & 7) << 4)));
            }
#pragma unroll
            for (int nt = 0; nt < 8; nt++)
                mma16816(acc[nt], af, bfr[nt >> 1][(nt & 1) * 2], bfr[nt >> 1][(nt & 1) * 2 + 1]);
        }
        __syncthreads();
    }

    float w1a = 0.f, w1b = 0.f, w2a = 0.f, w2b = 0.f;
#pragma unroll
    for (int nt = 0; nt < 8; nt++)
#pragma unroll
        for (int c = 0; c < 4; c++) {
            int feat = n0 + nt * 8 + (l & 3) * 2 + (c & 1);
            int row = i0 + m0 + (l >> 2) + (c >> 1) * 8;
            float v = acc[nt][c];
            uint16_t h8;
            asm("cvt.rn.satfinite.e4m3x2.f32 %0, %1, %2;" : "=h"(h8) : "f"(v), "f"(v));
            g_Wh8[(size_t)feat * NN + row] = (uint8_t)h8;
            float av1 = lds32f(sb + GSV + (uint32_t)feat * 4u);
            float av2 = lds32f(sb + GSV + (uint32_t)(128 + feat) * 4u);
            if ((c >> 1) == 0) { w1a = fmaf(v, av1, w1a); w2a = fmaf(v, av2, w2a); }
            else               { w1b = fmaf(v, av1, w1b); w2b = fmaf(v, av2, w2b); }
        }
#pragma unroll
    for (int s = 1; s <= 2; s <<= 1) {
        w1a += __shfl_xor_sync(0xffffffffu, w1a, s);
        w1b += __shfl_xor_sync(0xffffffffu, w1b, s);
        w2a += __shfl_xor_sync(0xffffffffu, w2a, s);
        w2b += __shfl_xor_sync(0xffffffffu, w2b, s);
    }
    // smem combine of the two n0-halves (warps 2k / 2k+1 share m0)
    if ((l & 3) == 0) {
        int rl = m0 + (l >> 2);                       // local row 0..63 (and +8)
        uint32_t h = (uint32_t)(w & 1) * 4u;
        sts32f(sb + GSR + (uint32_t)rl * 8u + h, w1a);
        sts32f(sb + GSR + (uint32_t)(rl + 8) * 8u + h, w1b);
        sts32f(sb + GSR + 512u + (uint32_t)rl * 8u + h, w2a);
        sts32f(sb + GSR + 512u + (uint32_t)(rl + 8) * 8u + h, w2b);
    }
    __syncthreads();
    if (t < 64) {
        g_Wh1[i0 + t] = lds32f(sb + GSR + (uint32_t)t * 8u)
                      + lds32f(sb + GSR + (uint32_t)t * 8u + 4u);
        g_Wh2[i0 + t] = lds32f(sb + GSR + 512u + (uint32_t)t * 8u)
                      + lds32f(sb + GSR + 512u + (uint32_t)t * 8u + 4u);
    }
}

// ================= K2: fused attention + finalize — FP8 mma, no splits =================
// CTA: 32 rows x 8192 j (64 tiles), grid 256, 2 CTAs/SM. 8 warps; warp tile 16x32.
// den via ones-mma (warps 0,1) -> smem; epilogue applies elu((num/den + rnd)*1e-5).

#define SP0   0u                     // P: 2 x 4KB
#define SB0   8192u                  // B: 2 x 16KB
#define SWS   40960u                 // ws half2: 16KB
#define SRED  57344u                 // reduction scratch
#define SM_DYN (57344 + 256)
#define ONES8 0x38383838u   // e4m3 1.0 x4
#define NTILE 64

__device__ __forceinline__ void issue_B(uint32_t sb, const uint8_t* wh8, int t, int tt) {
    const uint32_t bbase = sb + SB0 + (uint32_t)(tt & 1) * 16384u;
#pragma unroll
    for (int s = 0; s < 4; s++) {
        int c = t + s * 256;
        int f = c >> 3, u = c & 7;
        cp16(bbase + (uint32_t)f * 128u + (((uint32_t)u * 16u) ^ ((uint32_t)(f & 7) << 4)),
             wh8 + (size_t)f * NN + tt * 128 + u * 16);
    }
    asm volatile("cp.async.commit_group;" ::: "memory");
}

__global__ void __launch_bounds__(256, 2) k_attn(const int* __restrict__ adj,
                                                 const float* __restrict__ rnd,
                                                 float* __restrict__ out) {
    extern __shared__ char dsm[];
    uint32_t sb = (uint32_t)__cvta_generic_to_shared(dsm);
    sb = (sb + 127u) & ~127u;

    const int t = threadIdx.x, w = t >> 5, l = t & 31;
    const int i0 = blockIdx.x * 32;

    const uint8_t* wh8 = g_Wh8;

    // stage ws = 8log2e*Wh2 as half2 (16KB for all 8192 j), tracking global max
    float vmax = -1e30f;
    for (int x = t * 4; x < 8192; x += 1024) {
        float4 v = *reinterpret_cast<const float4*>(&g_Wh2[x]);
        uint32_t h01 = fh2(K8L2E * v.y, K8L2E * v.x);
        uint32_t h23 = fh2(K8L2E * v.w, K8L2E * v.z);
        sts64(sb + SWS + (uint32_t)x * 2u, h01, h23);
        vmax = fmaxf(fmaxf(vmax, fmaxf(v.x, v.y)), fmaxf(v.z, v.w));
    }

    issue_B(sb, wh8, t, 0);

    // M2 reduction (global; computed redundantly per CTA)
#pragma unroll
    for (int s = 16; s > 0; s >>= 1) vmax = fmaxf(vmax, __shfl_xor_sync(0xffffffffu, vmax, s));
    if (l == 0) sts32f(sb + SRED + (uint32_t)w * 4u, vmax);
    __syncthreads();
    float M2 = lds32f(sb + SRED);
#pragma unroll
    for (int i = 1; i < 8; i++) M2 = fmaxf(M2, lds32f(sb + SRED + (uint32_t)i * 4u));

    // build rows: 4 per warp; per-row half2 log-domain constants
    const int rbase = w * 4;
    uint32_t c1h[4], c2h[4];
#pragma unroll
    for (int r = 0; r < 4; r++) {
        float wh1 = g_Wh1[i0 + rbase + r];
        float s = wh1 + M2;
        s = fmaxf(s, 0.2f * s);                 // s_i (max attainable lrelu)
        float C = fmaf(-K8L2E, s, 120.0f);      // byte offset: 120 - 8log2e*s_i
        c1h[r] = f2h2(fmaf(K8L2E, wh1, C));
        c2h[r] = f2h2(fmaf(K8L2E5, wh1, C));
    }

    const int* adjbase = adj + (size_t)(i0 + rbase) * NN + l * 4;
    int4 ar[4];
#pragma unroll
    for (int u = 0; u < 4; u++) ar[u] = *reinterpret_cast<const int4*>(adjbase + (size_t)u * NN);

    // MMA warp tile: rows m0..m0+16, feats n0..n0+32
    const int m0 = (w & 1) * 16, n0 = (w >> 1) * 32;
    const int q = l >> 3, lq = l & 7;
    const int arow = m0 + (q & 1) * 8 + lq;
    const uint32_t paA = (uint32_t)arow * 128u;
    const uint32_t keyA = (uint32_t)(arow & 7) << 4;
    const int nfeat = n0 + (q & 1) * 8 + lq;
    const uint32_t paB = (uint32_t)nfeat * 128u;
    const uint32_t keyB = (uint32_t)(nfeat & 7) << 4;
    const uint32_t offK = (uint32_t)(q >> 1) * 16u;

    const uint32_t pst = ((uint32_t)(l >> 2) * 16u);
    const uint32_t pst_lo = ((uint32_t)(l & 3) << 2);

    float acc[4][4];
#pragma unroll
    for (int nt = 0; nt < 4; nt++)
#pragma unroll
        for (int c = 0; c < 4; c++) acc[nt][c] = 0.f;
    float accd[4] = {0.f, 0.f, 0.f, 0.f};      // den (warps 0,1 only)

    __syncthreads();   // staged vectors visible

    // ---- prologue: build P(0) into buf0, prefetch adj(1) ----
    {
        uint2 ws = lds64u(sb + SWS + (uint32_t)l * 8u);
        const int* nb = adjbase + 128;
#pragma unroll
        for (int r = 0; r < 4; r++) {
            int row = rbase + r;
            uint32_t pk = build4h(ws.x, ws.y, c1h[r], c2h[r], ar[r]);
            uint32_t paddr = sb + SP0 + (uint32_t)row * 128u
                           + (pst ^ ((uint32_t)(row & 7) << 4)) + pst_lo;
            sts32u(paddr, pk);
            ar[r] = *reinterpret_cast<const int4*>(nb + (size_t)r * NN);
        }
    }

#pragma unroll 1
    for (int tt = 0; tt < NTILE; tt++) {
        asm volatile("cp.async.wait_group 0;" ::: "memory");
        __syncthreads();               // B(tt) + P(tt) visible; old bufs free
        if (tt < NTILE - 1) issue_B(sb, wh8, t, tt + 1);

        const uint32_t sA  = sb + SP0 + (uint32_t)(tt & 1) * 4096u;
        const uint32_t sPn = sb + SP0 + (uint32_t)((tt + 1) & 1) * 4096u;
        const uint32_t sB  = sb + SB0 + (uint32_t)(tt & 1) * 16384u;

        uint2 ws;
        if (tt < NTILE - 1) ws = lds64u(sb + SWS + (uint32_t)((tt + 1) * 128 + l * 4) * 2u);
        const int* nb = adjbase + (tt + 2) * 128;

#pragma unroll
        for (int kk = 0; kk < 4; kk++) {
            // ---- mma chunk (reads P(tt), B(tt)) ----
            uint32_t ca = ((uint32_t)kk * 32u + offK);
            uint32_t af[4];
            ldsm4(af, sA + paA + (ca ^ keyA));
            uint32_t bfr[2][4];
#pragma unroll
            for (int i = 0; i < 2; i++)
                ldsm4(bfr[i], sB + paB + (uint32_t)i * 2048u + (ca ^ keyB));
#pragma unroll
            for (int nt = 0; nt < 4; nt++) {
                uint32_t b0 = bfr[nt >> 1][nt & 1];
                uint32_t b1 = bfr[nt >> 1][2 + (nt & 1)];
                mma_fp8(acc[nt], af, b0, b1);
            }
            if (w < 2) mma_fp8(accd, af, ONES8, ONES8);   // den row-sums

            // ---- build 1 row of P(tt+1), prefetch adj(tt+2) ----
            if (tt < NTILE - 1) {
                int r = kk;
                int row = rbase + r;
                uint32_t pk = build4h(ws.x, ws.y, c1h[r], c2h[r], ar[r]);
                uint32_t paddr = sPn + (uint32_t)row * 128u
                               + (pst ^ ((uint32_t)(row & 7) << 4)) + pst_lo;
                sts32u(paddr, pk);
                if (tt <= NTILE - 3) ar[r] = *reinterpret_cast<const int4*>(nb + (size_t)r * NN);
            }
        }
    }

    // ---- den to smem (warps 0,1 own rows 0..31 via m0 = w*16) ----
    if (w < 2 && (l & 3) == 0) {
        int rl = m0 + (l >> 2);
        sts32f(sb + SP0 + (uint32_t)rl * 4u, accd[0]);
        sts32f(sb + SP0 + (uint32_t)(rl + 8) * 4u, accd[2]);
    }
    __syncthreads();

    // ---- fused finalize: out = elu((num/den + rnd) * 1e-5) ----
    {
        float rdn0 = 1.0f / lds32f(sb + SP0 + (uint32_t)(m0 + (l >> 2)) * 4u);
        float rdn1 = 1.0f / lds32f(sb + SP0 + (uint32_t)(m0 + 8 + (l >> 2)) * 4u);
        int row0 = i0 + m0 + (l >> 2);
#pragma unroll
        for (int nt = 0; nt < 4; nt++) {
            int feat = n0 + nt * 8 + (l & 3) * 2;
            size_t idx0 = (size_t)row0 * OF + feat;
            size_t idx1 = idx0 + 8 * OF;
            float2 r0 = *reinterpret_cast<const float2*>(&rnd[idx0]);
            float2 r1 = *reinterpret_cast<const float2*>(&rnd[idx1]);
            float v0 = (acc[nt][0] * rdn0 + r0.x) * 1e-5f;
            float v1 = (acc[nt][1] * rdn0 + r0.y) * 1e-5f;
            float v2 = (acc[nt][2] * rdn1 + r1.x) * 1e-5f;
            float v3 = (acc[nt][3] * rdn1 + r1.y) * 1e-5f;
            float2 o0, o1;
            o0.x = v0 > 0.f ? v0 : expm1f(v0);
            o0.y = v1 > 0.f ? v1 : expm1f(v1);
            o1.x = v2 > 0.f ? v2 : expm1f(v2);
            o1.y = v3 > 0.f ? v3 : expm1f(v3);
            *reinterpret_cast<float2*>(&out[idx0]) = o0;
            *reinterpret_cast<float2*>(&out[idx1]) = o1;
        }
    }
}

// ================= launch =================
extern "C" void kernel_launch(void* const* d_in, const int* in_sizes, int n_in,
                              void* d_out, int out_size) {
    const float* h   = (const float*)d_in[0];
    const int*   adj = (const int*)d_in[1];
    const float* W   = (const float*)d_in[2];
    const float* a   = (const float*)d_in[3];
    const float* rnd = (const float*)d_in[4];
    float* out = (float*)d_out;

    cudaFuncSetAttribute(k_gemm, cudaFuncAttributeMaxDynamicSharedMemorySize, GSM);
    cudaFuncSetAttribute(k_attn, cudaFuncAttributeMaxDynamicSharedMemorySize, SM_DYN);

    k_prep<<<64, 256>>>(W);
    k_gemm<<<128, 256, GSM>>>(a, h);
    k_attn<<<256, 256, SM_DYN>>>(adj, rnd, out);
}

// round 17
// speedup vs baseline: 1.3364x; 1.3364x over previous
#include <cuda_runtime.h>
#include <cuda_bf16.h>
#include <cstdint>

#define NN 8192
#define INF 512
#define OF 128

// ---------------- scratch (device globals; no allocation) ----------------
__device__ __nv_bfloat16 g_WT[(size_t)OF * INF];   // W^T bf16 [feat][k]
__device__ uint8_t g_Wh8[(size_t)OF * NN];         // Wh e4m3 [feat][node]
__device__ float g_Wh1[NN];
__device__ float g_Wh2[NN];
__device__ float g_M2s[2];                         // per-split max_j Wh2[j]
__device__ float g_num[(size_t)2 * NN * OF];       // [split][node][feat]
__device__ float g_den[2 * NN];                    // [split][node]

#define K8L2E 11.541560327111708f    // 8*log2(e)
#define K8L2E5 2.3083120654223416f   // 0.2 * 8*log2(e)
#define K02H2  0x32663266u           // half2(0.2, 0.2)
#define MAGIC2 0x64006400u           // half2(1024.0, 1024.0)

// ---------------- helpers ----------------
__device__ __forceinline__ uint32_t pack2(float lo, float hi) {
    uint32_t r;
    asm("cvt.rn.bf16x2.f32 %0, %1, %2;" : "=r"(r) : "f"(hi), "f"(lo));
    return r;
}
__device__ __forceinline__ uint32_t f2h2(float v) {
    uint32_t r;
    asm("{ .reg .f16 h; cvt.rn.f16.f32 h, %1; mov.b32 %0, {h, h}; }" : "=r"(r) : "f"(v));
    return r;
}
__device__ __forceinline__ uint32_t fh2(float hi, float lo) {
    uint32_t r;
    asm("cvt.rn.f16x2.f32 %0, %1, %2;" : "=r"(r) : "f"(hi), "f"(lo));
    return r;
}
__device__ __forceinline__ void sts32u(uint32_t a, uint32_t v) {
    asm volatile("st.shared.b32 [%0], %1;" :: "r"(a), "r"(v) : "memory");
}
__device__ __forceinline__ void sts32f(uint32_t a, float v) {
    asm volatile("st.shared.f32 [%0], %1;" :: "r"(a), "f"(v) : "memory");
}
__device__ __forceinline__ void sts64(uint32_t a, uint32_t x, uint32_t y) {
    asm volatile("st.shared.v2.b32 [%0], {%1,%2};" :: "r"(a), "r"(x), "r"(y) : "memory");
}
__device__ __forceinline__ void sts128u(uint32_t a, uint32_t x, uint32_t y,
                                        uint32_t z, uint32_t w) {
    asm volatile("st.shared.v4.b32 [%0], {%1,%2,%3,%4};"
                 :: "r"(a), "r"(x), "r"(y), "r"(z), "r"(w) : "memory");
}
__device__ __forceinline__ float lds32f(uint32_t a) {
    float v; asm volatile("ld.shared.f32 %0, [%1];" : "=f"(v) : "r"(a)); return v;
}
__device__ __forceinline__ uint2 lds64u(uint32_t a) {
    uint2 v;
    asm volatile("ld.shared.v2.b32 {%0,%1}, [%2];" : "=r"(v.x), "=r"(v.y) : "r"(a));
    return v;
}
__device__ __forceinline__ void ldsm4(uint32_t* r, uint32_t a) {
    asm volatile("ldmatrix.sync.aligned.m8n8.x4.shared.b16 {%0,%1,%2,%3}, [%4];"
                 : "=r"(r[0]), "=r"(r[1]), "=r"(r[2]), "=r"(r[3]) : "r"(a));
}
__device__ __forceinline__ void mma16816(float* d, const uint32_t* a, uint32_t b0, uint32_t b1) {
    asm volatile(
        "mma.sync.aligned.m16n8k16.row.col.f32.bf16.bf16.f32 "
        "{%0,%1,%2,%3}, {%4,%5,%6,%7}, {%8,%9}, {%0,%1,%2,%3};"
        : "+f"(d[0]), "+f"(d[1]), "+f"(d[2]), "+f"(d[3])
        : "r"(a[0]), "r"(a[1]), "r"(a[2]), "r"(a[3]), "r"(b0), "r"(b1));
}
__device__ __forceinline__ void mma_fp8(float* d, const uint32_t* a, uint32_t b0, uint32_t b1) {
    asm volatile(
        "mma.sync.aligned.m16n8k32.row.col.f32.e4m3.e4m3.f32 "
        "{%0,%1,%2,%3}, {%4,%5,%6,%7}, {%8,%9}, {%0,%1,%2,%3};"
        : "+f"(d[0]), "+f"(d[1]), "+f"(d[2]), "+f"(d[3])
        : "r"(a[0]), "r"(a[1]), "r"(a[2]), "r"(a[3]), "r"(b0), "r"(b1));
}
__device__ __forceinline__ void cp16(uint32_t s, const void* g) {
    asm volatile("cp.async.cg.shared.global [%0], [%1], 16;" :: "r"(s), "l"(g) : "memory");
}
// half2 log-domain build: byte = round(max(max(ws+c1, 0.2*ws+c2), 0)) via +1024 magic
__device__ __forceinline__ uint32_t build4h(uint32_t ws01, uint32_t ws23,
                                            uint32_t c1, uint32_t c2, int4 a4) {
    uint32_t t0, t1, m0, m1;
    asm("add.f16x2 %0, %1, %2;" : "=r"(t0) : "r"(ws01), "r"(c1));
    asm("fma.rn.f16x2 %0, %1, %2, %3;" : "=r"(t1) : "r"(ws01), "r"(K02H2), "r"(c2));
    asm("max.f16x2 %0, %1, %2;" : "=r"(m0) : "r"(t0), "r"(t1));
    asm("max.f16x2 %0, %1, %2;" : "=r"(m0) : "r"(m0), "r"(0u));
    asm("add.f16x2 %0, %1, %2;" : "=r"(m0) : "r"(m0), "r"(MAGIC2));
    asm("add.f16x2 %0, %1, %2;" : "=r"(t0) : "r"(ws23), "r"(c1));
    asm("fma.rn.f16x2 %0, %1, %2, %3;" : "=r"(t1) : "r"(ws23), "r"(K02H2), "r"(c2));
    asm("max.f16x2 %0, %1, %2;" : "=r"(m1) : "r"(t0), "r"(t1));
    asm("max.f16x2 %0, %1, %2;" : "=r"(m1) : "r"(m1), "r"(0u));
    asm("add.f16x2 %0, %1, %2;" : "=r"(m1) : "r"(m1), "r"(MAGIC2));
    uint32_t pk = __byte_perm(m0, m1, 0x6420);   // mantissa byte0 of each half lane
    uint32_t m = __byte_perm(__byte_perm(a4.x, a4.y, 0x0040),
                             __byte_perm(a4.z, a4.w, 0x0040), 0x5410);
    return pk & (m * 255u);
}

// ================= K0: prep — W->W^T bf16 (smem tile transpose), zero Wh1/Wh2 =====
__global__ __launch_bounds__(256) void k_prep(const float* __restrict__ W) {
    const int b = blockIdx.x, t = threadIdx.x;
    if (b < 64) {
        // tile (kt, ft): 32x32; 16 kt x 4 ft
        __shared__ float sm[32][33];
        const int kt = b >> 2, ft = b & 3;
        const int k0 = kt * 32, f0 = ft * 32;
        // coalesced load: row r = t/8, cols (t%8)*4
        {
            int r = t >> 3, c0 = (t & 7) * 4;
            float4 v = *reinterpret_cast<const float4*>(&W[(size_t)(k0 + r) * OF + f0 + c0]);
            sm[r][c0] = v.x; sm[r][c0 + 1] = v.y; sm[r][c0 + 2] = v.z; sm[r][c0 + 3] = v.w;
        }
        __syncthreads();
        // coalesced store: WT row f = f0 + t/8, k chunk (t%8)*4 (8 bytes)
        {
            int fl = t >> 3, kq = (t & 7) * 4;
            uint2 p = make_uint2(pack2(sm[kq][fl], sm[kq + 1][fl]),
                                 pack2(sm[kq + 2][fl], sm[kq + 3][fl]));
            *reinterpret_cast<uint2*>(&g_WT[(size_t)(f0 + fl) * INF + k0 + kq]) = p;
        }
    } else {   // zero Wh1/Wh2 (atomicAdd targets; every replay)
#pragma unroll
        for (int u = 0; u < 32; u++) { g_Wh1[u * 256 + t] = 0.f; g_Wh2[u * 256 + t] = 0.f; }
    }
}

// ================= K1: Wh = h @ W via bf16 mma.sync, + Wh1/Wh2 =================
// A staged from f32 h via LDG + in-register bf16 convert + STS (register double-buffer).
#define GSA 0u
#define GSB 16384u
#define GSV 49152u
#define GSM (49152 + 1024 + 128)

__device__ __forceinline__ void issue_Bg(uint32_t sb, int ko, int t) {
    const uint32_t bbuf = sb + GSB + (uint32_t)(ko & 1) * 16384u;
#pragma unroll
    for (int s = 0; s < 4; s++) {
        int c = t + s * 256;
        int f = c >> 3, u = c & 7;
        cp16(bbuf + (uint32_t)f * 128u + (((uint32_t)u * 16u) ^ ((uint32_t)(f & 7) << 4)),
             &g_WT[(size_t)f * INF + ko * 64 + u * 8]);
    }
    asm volatile("cp.async.commit_group;" ::: "memory");
}
__device__ __forceinline__ void lda2(float4* d, const float* __restrict__ h,
                                     int i0, int ko, int t) {
#pragma unroll
    for (int s = 0; s < 2; s++) {
        int c = t + s * 256;
        int r = c >> 3, u = c & 7;
        const float* src = &h[(size_t)(i0 + r) * INF + ko * 64 + u * 8];
        d[s * 2]     = *reinterpret_cast<const float4*>(src);
        d[s * 2 + 1] = *reinterpret_cast<const float4*>(src + 4);
    }
}
__device__ __forceinline__ void sta2(uint32_t sb, int ko, int t, const float4* d) {
    const uint32_t abuf = sb + GSA + (uint32_t)(ko & 1) * 8192u;
#pragma unroll
    for (int s = 0; s < 2; s++) {
        int c = t + s * 256;
        int r = c >> 3, u = c & 7;
        sts128u(abuf + (uint32_t)r * 128u + (((uint32_t)u * 16u) ^ ((uint32_t)(r & 7) << 4)),
                pack2(d[s * 2].x, d[s * 2].y), pack2(d[s * 2].z, d[s * 2].w),
                pack2(d[s * 2 + 1].x, d[s * 2 + 1].y), pack2(d[s * 2 + 1].z, d[s * 2 + 1].w));
    }
}

__global__ void __launch_bounds__(256, 1) k_gemm(const float* __restrict__ a,
                                                 const float* __restrict__ h) {
    extern __shared__ char dsm[];
    uint32_t sb = (uint32_t)__cvta_generic_to_shared(dsm);
    sb = (sb + 127u) & ~127u;

    const int t = threadIdx.x, w = t >> 5, l = t & 31;
    const int i0 = blockIdx.x * 64;
    const int m0 = (w >> 1) * 16, n0 = (w & 1) * 64;

    if (t < 256) sts32f(sb + GSV + (uint32_t)t * 4u, a[t]);

    float4 ra[4];
    lda2(ra, h, i0, 0, t);
    sta2(sb, 0, t, ra);            // A(0) -> buf0
    lda2(ra, h, i0, 1, t);         // prefetch A(1)
    issue_Bg(sb, 0, t);

    const int q = l >> 3, lq = l & 7;
    const uint32_t keyL = (uint32_t)lq << 4;
    const int arow = m0 + (q & 1) * 8 + lq;
    const uint32_t paA = (uint32_t)arow * 128u;
    const uint32_t offA = ((uint32_t)(q >> 1) * 16u);
    const int bq_f = (q >> 1) * 8 + lq;
    const uint32_t offBk = ((uint32_t)(q & 1) * 16u);

    float acc[8][4];
#pragma unroll
    for (int nt = 0; nt < 8; nt++)
#pragma unroll
        for (int c = 0; c < 4; c++) acc[nt][c] = 0.f;

#pragma unroll 1
    for (int ko = 0; ko < 8; ko++) {
        asm volatile("cp.async.wait_group 0;" ::: "memory");
        __syncthreads();
        if (ko < 7) {
            issue_Bg(sb, ko + 1, t);
            sta2(sb, ko + 1, t, ra);           // A(ko+1) -> other buf
        }
        if (ko < 6) lda2(ra, h, i0, ko + 2, t);  // prefetch A(ko+2)

        const uint32_t abuf = sb + GSA + (uint32_t)(ko & 1) * 8192u;
        const uint32_t bbuf = sb + GSB + (uint32_t)(ko & 1) * 16384u;
#pragma unroll
        for (int kk = 0; kk < 4; kk++) {
            uint32_t af[4];
            ldsm4(af, abuf + paA + (((uint32_t)kk * 32u + offA) ^ keyL));
            uint32_t bfr[4][4];
#pragma unroll
            for (int i = 0; i < 4; i++) {
                int f = n0 + i * 16 + bq_f;
                ldsm4(bfr[i], bbuf + (uint32_t)f * 128u
                              + (((uint32_t)kk * 32u + offBk) ^ ((uint32_t)(f & 7) << 4)));
            }
#pragma unroll
            for (int nt = 0; nt < 8; nt++)
                mma16816(acc[nt], af, bfr[nt >> 1][(nt & 1) * 2], bfr[nt >> 1][(nt & 1) * 2 + 1]);
        }
        __syncthreads();
    }

    float w1a = 0.f, w1b = 0.f, w2a = 0.f, w2b = 0.f;
#pragma unroll
    for (int nt = 0; nt < 8; nt++)
#pragma unroll
        for (int c = 0; c < 4; c++) {
            int feat = n0 + nt * 8 + (l & 3) * 2 + (c & 1);
            int row = i0 + m0 + (l >> 2) + (c >> 1) * 8;
            float v = acc[nt][c];
            uint16_t h8;
            asm("cvt.rn.satfinite.e4m3x2.f32 %0, %1, %2;" : "=h"(h8) : "f"(v), "f"(v));
            g_Wh8[(size_t)feat * NN + row] = (uint8_t)h8;
            float av1 = lds32f(sb + GSV + (uint32_t)feat * 4u);
            float av2 = lds32f(sb + GSV + (uint32_t)(128 + feat) * 4u);
            if ((c >> 1) == 0) { w1a = fmaf(v, av1, w1a); w2a = fmaf(v, av2, w2a); }
            else               { w1b = fmaf(v, av1, w1b); w2b = fmaf(v, av2, w2b); }
        }
#pragma unroll
    for (int s = 1; s <= 2; s <<= 1) {
        w1a += __shfl_xor_sync(0xffffffffu, w1a, s);
        w1b += __shfl_xor_sync(0xffffffffu, w1b, s);
        w2a += __shfl_xor_sync(0xffffffffu, w2a, s);
        w2b += __shfl_xor_sync(0xffffffffu, w2b, s);
    }
    if ((l & 3) == 0) {
        int r0 = i0 + m0 + (l >> 2);
        atomicAdd(&g_Wh1[r0], w1a);     atomicAdd(&g_Wh2[r0], w2a);
        atomicAdd(&g_Wh1[r0 + 8], w1b); atomicAdd(&g_Wh2[r0 + 8], w2b);
    }
}

// ================= K2: fused attention — FP8 mma, half2 log-domain build =================
// CTA: 64 rows x 4096 j (32 tiles), 2 CTAs/SM. 8 warps; warp tile 16x64.
// Split-local softmax shift (M2 reduced in-prologue); splits merged in k_final.

#define SP0   0u
#define SB0   16384u
#define SWS   49152u
#define SRED  57344u                 // reduction scratch (pad area)
#define SM_DYN (57344 + 256)
#define ONES8 0x38383838u   // e4m3 1.0 x4
#define NTILE 32

__device__ __forceinline__ void issue_B(uint32_t sb, const uint8_t* wh8, int t, int tt) {
    const uint32_t bbase = sb + SB0 + (uint32_t)(tt & 1) * 16384u;
#pragma unroll
    for (int s = 0; s < 4; s++) {
        int c = t + s * 256;
        int f = c >> 3, u = c & 7;
        cp16(bbase + (uint32_t)f * 128u + (((uint32_t)u * 16u) ^ ((uint32_t)(f & 7) << 4)),
             wh8 + (size_t)f * NN + tt * 128 + u * 16);
    }
    asm volatile("cp.async.commit_group;" ::: "memory");
}

__global__ void __launch_bounds__(256, 2) k_attn(const int* __restrict__ adj) {
    extern __shared__ char dsm[];
    uint32_t sb = (uint32_t)__cvta_generic_to_shared(dsm);
    sb = (sb + 127u) & ~127u;

    const int t = threadIdx.x, w = t >> 5, l = t & 31;
    const int rb = blockIdx.x >> 1, split = blockIdx.x & 1;
    const int i0 = rb * 64, jb = split * 4096;

    const uint8_t* wh8 = g_Wh8 + jb;

    // stage ws = 8log2e*Wh2 as half2 (8KB), tracking split-local max of Wh2
    float vmax = -1e30f;
    for (int x = t * 4; x < 4096; x += 1024) {
        float4 v = *reinterpret_cast<const float4*>(&g_Wh2[jb + x]);
        uint32_t h01 = fh2(K8L2E * v.y, K8L2E * v.x);
        uint32_t h23 = fh2(K8L2E * v.w, K8L2E * v.z);
        sts64(sb + SWS + (uint32_t)x * 2u, h01, h23);
        vmax = fmaxf(fmaxf(vmax, fmaxf(v.x, v.y)), fmaxf(v.z, v.w));
    }

    issue_B(sb, wh8, t, 0);

    // split-local M2 reduction
#pragma unroll
    for (int s = 16; s > 0; s >>= 1) vmax = fmaxf(vmax, __shfl_xor_sync(0xffffffffu, vmax, s));
    if (l == 0) sts32f(sb + SRED + (uint32_t)w * 4u, vmax);
    __syncthreads();
    float M2 = lds32f(sb + SRED);
#pragma unroll
    for (int i = 1; i < 8; i++) M2 = fmaxf(M2, lds32f(sb + SRED + (uint32_t)i * 4u));
    if (t == 0) g_M2s[split] = M2;   // same value from every CTA of this split

    // build rows: 8 per warp; per-row half2 log-domain constants
    const int rbase = w * 8;
    uint32_t c1h[8], c2h[8];
#pragma unroll
    for (int r = 0; r < 8; r++) {
        float wh1 = g_Wh1[i0 + rbase + r];
        float s = wh1 + M2;
        s = fmaxf(s, 0.2f * s);                 // s_i (max attainable lrelu, this split)
        float C = fmaf(-K8L2E, s, 120.0f);      // byte offset: 120 - 8log2e*s_i
        c1h[r] = f2h2(fmaf(K8L2E, wh1, C));
        c2h[r] = f2h2(fmaf(K8L2E5, wh1, C));
    }

    const int* adjbase = adj + (size_t)(i0 + rbase) * NN + jb + l * 4;
    int4 ar[8];
#pragma unroll
    for (int u = 0; u < 8; u++) ar[u] = *reinterpret_cast<const int4*>(adjbase + (size_t)u * NN);

    // MMA warp tile: rows m0..m0+16, feats n0..n0+64
    const int m0 = (w & 3) * 16, n0 = (w >> 2) * 64;
    const int q = l >> 3, lq = l & 7;
    const int arow = m0 + (q & 1) * 8 + lq;
    const uint32_t paA = (uint32_t)arow * 128u;
    const uint32_t keyA = (uint32_t)(arow & 7) << 4;
    const int nfeat = n0 + (q & 1) * 8 + lq;
    const uint32_t paB = (uint32_t)nfeat * 128u;
    const uint32_t keyB = (uint32_t)(nfeat & 7) << 4;
    const uint32_t offK = (uint32_t)(q >> 1) * 16u;

    const uint32_t pst = ((uint32_t)(l >> 2) * 16u);
    const uint32_t pst_lo = ((uint32_t)(l & 3) << 2);

    float acc[8][4];
#pragma unroll
    for (int nt = 0; nt < 8; nt++)
#pragma unroll
        for (int c = 0; c < 4; c++) acc[nt][c] = 0.f;
    float accd[4] = {0.f, 0.f, 0.f, 0.f};      // den (warps w<4 only)

    __syncthreads();   // staged vectors visible (also covers SRED reads)

    // ---- prologue: build P(0) into buf0, prefetch adj(1) ----
    {
        uint2 ws = lds64u(sb + SWS + (uint32_t)l * 8u);
        const int* nb = adjbase + 128;
#pragma unroll
        for (int r = 0; r < 8; r++) {
            int row = rbase + r;
            uint32_t pk = build4h(ws.x, ws.y, c1h[r], c2h[r], ar[r]);
            uint32_t paddr = sb + SP0 + (uint32_t)row * 128u
                           + (pst ^ ((uint32_t)(row & 7) << 4)) + pst_lo;
            sts32u(paddr, pk);
            ar[r] = *reinterpret_cast<const int4*>(nb + (size_t)r * NN);
        }
    }

#pragma unroll 1
    for (int tt = 0; tt < NTILE; tt++) {
        asm volatile("cp.async.wait_group 0;" ::: "memory");
        __syncthreads();               // B(tt) + P(tt) visible; old bufs free
        if (tt < NTILE - 1) issue_B(sb, wh8, t, tt + 1);

        const uint32_t sA  = sb + SP0 + (uint32_t)(tt & 1) * 8192u;
        const uint32_t sPn = sb + SP0 + (uint32_t)((tt + 1) & 1) * 8192u;
        const uint32_t sB  = sb + SB0 + (uint32_t)(tt & 1) * 16384u;

        uint2 ws;
        if (tt < NTILE - 1) ws = lds64u(sb + SWS + (uint32_t)((tt + 1) * 128 + l * 4) * 2u);
        const int* nb = adjbase + (tt + 2) * 128;

#pragma unroll
        for (int kk = 0; kk < 4; kk++) {
            // ---- mma chunk (reads P(tt), B(tt)) ----
            uint32_t ca = ((uint32_t)kk * 32u + offK);
            uint32_t af[4];
            ldsm4(af, sA + paA + (ca ^ keyA));
            uint32_t bfr[4][4];
#pragma unroll
            for (int i = 0; i < 4; i++)
                ldsm4(bfr[i], sB + paB + (uint32_t)i * 2048u + (ca ^ keyB));
#pragma unroll
            for (int nt = 0; nt < 8; nt++) {
                uint32_t b0 = bfr[nt >> 1][nt & 1];
                uint32_t b1 = bfr[nt >> 1][2 + (nt & 1)];
                mma_fp8(acc[nt], af, b0, b1);
            }
            if (w < 4) mma_fp8(accd, af, ONES8, ONES8);   // den row-sums

            // ---- build 2 rows of P(tt+1), prefetch adj(tt+2) ----
            if (tt < NTILE - 1) {
#pragma unroll
                for (int rr = 0; rr < 2; rr++) {
                    int r = kk * 2 + rr;
                    int row = rbase + r;
                    uint32_t pk = build4h(ws.x, ws.y, c1h[r], c2h[r], ar[r]);
                    uint32_t paddr = sPn + (uint32_t)row * 128u
                                   + (pst ^ ((uint32_t)(row & 7) << 4)) + pst_lo;
                    sts32u(paddr, pk);
                    if (tt <= NTILE - 3) ar[r] = *reinterpret_cast<const int4*>(nb + (size_t)r * NN);
                }
            }
        }
    }

    // ---- den epilogue: warps w<4 own rows m0 = w*16; cols identical (B=ones) ----
    if (w < 4 && (l & 3) == 0) {
        int row = i0 + (w & 3) * 16 + (l >> 2);
        g_den[split * NN + row] = accd[0];
        g_den[split * NN + row + 8] = accd[2];
    }

    // ---- num epilogue ----
#pragma unroll
    for (int nt = 0; nt < 8; nt++) {
        int row = i0 + m0 + (l >> 2);
        int feat = n0 + nt * 8 + (l & 3) * 2;
        float* b = &g_num[((size_t)split * NN + row) * OF + feat];
        b[0] = acc[nt][0];
        b[1] = acc[nt][1];
        b[8 * OF] = acc[nt][2];
        b[8 * OF + 1] = acc[nt][3];
    }
}

// ================= K3: merge splits (per-split shifts), finalize — 8 elems/thread ====
__global__ __launch_bounds__(256) void k_final(const float* __restrict__ rnd,
                                               float* __restrict__ out) {
    int base = (blockIdx.x * 256 + threadIdx.x) * 8;
    int i = base >> 7;
    float wh1 = g_Wh1[i];
    float s0 = wh1 + g_M2s[0]; s0 = fmaxf(s0, 0.2f * s0);
    float s1 = wh1 + g_M2s[1]; s1 = fmaxf(s1, 0.2f * s1);
    float r = __expf(s1 - s0);
    float rden = 1.0f / (g_den[i] + r * g_den[NN + i]);

    float4 n0[2], n1[2], rv[2];
#pragma unroll
    for (int u = 0; u < 2; u++) {
        n0[u] = *reinterpret_cast<const float4*>(&g_num[base + u * 4]);
        n1[u] = *reinterpret_cast<const float4*>(&g_num[(size_t)NN * OF + base + u * 4]);
        rv[u] = *reinterpret_cast<const float4*>(&rnd[base + u * 4]);
    }
#pragma unroll
    for (int u = 0; u < 2; u++) {
        float v0 = (fmaf(r, n1[u].x, n0[u].x) * rden + rv[u].x) * 1e-5f;
        float v1 = (fmaf(r, n1[u].y, n0[u].y) * rden + rv[u].y) * 1e-5f;
        float v2 = (fmaf(r, n1[u].z, n0[u].z) * rden + rv[u].z) * 1e-5f;
        float v3 = (fmaf(r, n1[u].w, n0[u].w) * rden + rv[u].w) * 1e-5f;
        float4 o;
        o.x = v0 > 0.f ? v0 : expm1f(v0);
        o.y = v1 > 0.f ? v1 : expm1f(v1);
        o.z = v2 > 0.f ? v2 : expm1f(v2);
        o.w = v3 > 0.f ? v3 : expm1f(v3);
        *reinterpret_cast<float4*>(&out[base + u * 4]) = o;
    }
}

// ================= launch =================
extern "C" void kernel_launch(void* const* d_in, const int* in_sizes, int n_in,
                              void* d_out, int out_size) {
    const float* h   = (const float*)d_in[0];
    const int*   adj = (const int*)d_in[1];
    const float* W   = (const float*)d_in[2];
    const float* a   = (const float*)d_in[3];
    const float* rnd = (const float*)d_in[4];
    float* out = (float*)d_out;

    cudaFuncSetAttribute(k_gemm, cudaFuncAttributeMaxDynamicSharedMemorySize, GSM);
    cudaFuncSetAttribute(k_attn, cudaFuncAttributeMaxDynamicSharedMemorySize, SM_DYN);

    k_prep<<<65, 256>>>(W);
    k_gemm<<<128, 256, GSM>>>(a, h);
    k_attn<<<256, 256, SM_DYN>>>(adj);
    k_final<<<512, 256>>>(rnd, out);
}